// round 7
// baseline (speedup 1.0000x reference)
#include <cuda_runtime.h>
#include <math.h>

#define BB 32
#define SS 4096
#define HH 1024
#define NCHUNK 64
#define CHUNK (SS / NCHUNK)            // 64 rows per block
#define ROWS_PER_WARP (CHUNK / 8)      // 8 rows per warp
#define NEG_BIG -1.0e9f

// ---- scratch (no allocations allowed) ----
__device__ float g_qp[2 * BB * HH];               // split-K projected-query partials
__device__ float g_part_m[BB * NCHUNK];           // per-chunk running max
__device__ float g_part_l[BB * NCHUNK];           // per-chunk exp-sum
__device__ float g_part_acc[BB * NCHUNK * HH];    // per-chunk unnormalized context (8MB)

// ============================================================
// Kernel A: split-K projection. [UNCHANGED from R6 — 14.0us]
// grid (HH/4, 4, 2) = 2048 CTAs, 128 threads (4 warps).
// ============================================================
__global__ void __launch_bounds__(128) proj_kernel(
    const float* __restrict__ query, const float* __restrict__ W)
{
    const int tid = threadIdx.x;
    const int w = tid >> 5, lane = tid & 31;
    const int o = blockIdx.x * 4 + w;
    const int b0 = blockIdx.y * 8;
    const int z = blockIdx.z;                      // k-half
    const int h0 = z * (HH / 2);                   // 0 or 512

    const float4* wrow = (const float4*)(W + (size_t)o * HH + h0);
    float4 wv[4];
    #pragma unroll
    for (int j = 0; j < 4; j++) wv[j] = wrow[j * 32 + lane];

    float p[8];
    #pragma unroll
    for (int bb = 0; bb < 8; bb++) {
        const float4* qq = (const float4*)(query + (size_t)(b0 + bb) * HH + h0);
        float s = 0.f;
        #pragma unroll
        for (int j = 0; j < 4; j++) {
            float4 qv = __ldg(qq + j * 32 + lane);
            s += wv[j].x * qv.x + wv[j].y * qv.y + wv[j].z * qv.z + wv[j].w * qv.w;
        }
        p[bb] = s;
    }

    #pragma unroll
    for (int off = 16; off > 0; off >>= 1) {
        #pragma unroll
        for (int bb = 0; bb < 8; bb++)
            p[bb] += __shfl_xor_sync(0xffffffffu, p[bb], off);
    }
    if (lane == 0) {
        float* dst = g_qp + (size_t)z * BB * HH;
        #pragma unroll
        for (int bb = 0; bb < 8; bb++)
            dst[(size_t)(b0 + bb) * HH + o] = p[bb];
    }
}

// ============================================================
// Kernel B: fused scores + online softmax + context partial.
// grid (NCHUNK, B) = 2048 CTAs, 256 threads (8 warps).
// Warp processes ROW PAIRS: 64 loads issue together, two
// independent dot chains (2 partials each), two pipelined
// shfl trees, ONE batched softmax rescale per pair.
// ============================================================
__global__ void __launch_bounds__(256) flash_kernel(
    const float* __restrict__ keys,
    const int* __restrict__ mask,
    float* __restrict__ scores_out)
{
    const int chunk = blockIdx.x, b = blockIdx.y;
    const int tid = threadIdx.x, w = tid >> 5, lane = tid & 31;

    __shared__ float4 sq[HH / 4];          // 4KB projected query (sum of partials)
    __shared__ float  s_m[8], s_l[8];
    __shared__ float4 s_acc[8][256];       // 32KB warp partial contexts

    {
        const float4* q0 = (const float4*)(g_qp);
        const float4* q1 = (const float4*)(g_qp + (size_t)BB * HH);
        const size_t base = (size_t)b * (HH / 4);
        for (int i = tid; i < HH / 4; i += 256) {
            float4 a = q0[base + i], c = q1[base + i];
            sq[i] = make_float4(a.x + c.x, a.y + c.y, a.z + c.z, a.w + c.w);
        }
    }
    __syncthreads();

    float4 acc[8];
    #pragma unroll
    for (int j = 0; j < 8; j++) acc[j] = make_float4(0.f, 0.f, 0.f, 0.f);
    float m = -INFINITY, l = 0.f;

    const int s0 = chunk * CHUNK + w * ROWS_PER_WARP;
    const int* mrow = mask + (size_t)b * SS;
    const float4* kbase = (const float4*)(keys + ((size_t)b * SS + s0) * HH);

    #pragma unroll
    for (int rp = 0; rp < ROWS_PER_WARP / 2; rp++) {
        const int s = s0 + rp * 2;
        const float4* kp0 = kbase + (size_t)(rp * 2) * (HH / 4);
        const float4* kp1 = kp0 + (HH / 4);

        // issue all 64 loads for the pair before any consumer
        float4 kv0[8], kv1[8];
        #pragma unroll
        for (int j = 0; j < 8; j++) kv0[j] = __ldcs(kp0 + j * 32 + lane);
        #pragma unroll
        for (int j = 0; j < 8; j++) kv1[j] = __ldcs(kp1 + j * 32 + lane);

        // two independent dots, 2 partial accumulators each
        float a0 = 0.f, b0 = 0.f, a1 = 0.f, b1 = 0.f;
        #pragma unroll
        for (int j = 0; j < 8; j += 2) {
            float4 qe = sq[j * 32 + lane];
            float4 qo = sq[(j + 1) * 32 + lane];
            a0 += kv0[j].x * qe.x + kv0[j].y * qe.y + kv0[j].z * qe.z + kv0[j].w * qe.w;
            b0 += kv0[j+1].x * qo.x + kv0[j+1].y * qo.y + kv0[j+1].z * qo.z + kv0[j+1].w * qo.w;
            a1 += kv1[j].x * qe.x + kv1[j].y * qe.y + kv1[j].z * qe.z + kv1[j].w * qe.w;
            b1 += kv1[j+1].x * qo.x + kv1[j+1].y * qo.y + kv1[j+1].z * qo.z + kv1[j+1].w * qo.w;
        }
        float p0 = a0 + b0, p1 = a1 + b1;

        // two shfl trees, pipelined
        #pragma unroll
        for (int off = 16; off > 0; off >>= 1) {
            p0 += __shfl_xor_sync(0xffffffffu, p0, off);
            p1 += __shfl_xor_sync(0xffffffffu, p1, off);
        }

        const float sc0 = (mrow[s] != 0)     ? NEG_BIG : p0;
        const float sc1 = (mrow[s + 1] != 0) ? NEG_BIG : p1;
        if (lane == 0) {
            scores_out[(size_t)b * SS + s]     = sc0;
            scores_out[(size_t)b * SS + s + 1] = sc1;
        }

        // batched online softmax update (one rescale per pair)
        const float mn = fmaxf(m, fmaxf(sc0, sc1));
        const float c  = __expf(m - mn);       // exp(-inf)=0 on first pair
        const float e0 = __expf(sc0 - mn);
        const float e1 = __expf(sc1 - mn);
        l = l * c + e0 + e1;
        #pragma unroll
        for (int j = 0; j < 8; j++) {
            acc[j].x = acc[j].x * c + e0 * kv0[j].x + e1 * kv1[j].x;
            acc[j].y = acc[j].y * c + e0 * kv0[j].y + e1 * kv1[j].y;
            acc[j].z = acc[j].z * c + e0 * kv0[j].z + e1 * kv1[j].z;
            acc[j].w = acc[j].w * c + e0 * kv0[j].w + e1 * kv1[j].w;
        }
        m = mn;
    }

    // ---- combine 8 warps within the block ----
    if (lane == 0) { s_m[w] = m; s_l[w] = l; }
    #pragma unroll
    for (int j = 0; j < 8; j++) s_acc[w][j * 32 + lane] = acc[j];
    __syncthreads();

    float M = s_m[0];
    #pragma unroll
    for (int i = 1; i < 8; i++) M = fmaxf(M, s_m[i]);
    float ew[8], L = 0.f;
    #pragma unroll
    for (int i = 0; i < 8; i++) { ew[i] = __expf(s_m[i] - M); L += ew[i] * s_l[i]; }

    float4 cacc = make_float4(0.f, 0.f, 0.f, 0.f);
    #pragma unroll
    for (int i = 0; i < 8; i++) {
        float4 v = s_acc[i][tid];
        cacc.x += ew[i] * v.x; cacc.y += ew[i] * v.y;
        cacc.z += ew[i] * v.z; cacc.w += ew[i] * v.w;
    }
    const int pidx = b * NCHUNK + chunk;
    ((float4*)(g_part_acc + (size_t)pidx * HH))[tid] = cacc;
    if (tid == 0) { g_part_m[pidx] = M; g_part_l[pidx] = L; }
}

// ============================================================
// Kernel C: combine chunk partials -> context; normalize raw
// scores -> weights. grid (B, 9). [UNCHANGED]
// ============================================================
__global__ void __launch_bounds__(256) finalize_kernel(float* __restrict__ out)
{
    const int b = blockIdx.x, part = blockIdx.y, tid = threadIdx.x;

    float M = g_part_m[b * NCHUNK];
    #pragma unroll
    for (int c = 1; c < NCHUNK; c++) M = fmaxf(M, g_part_m[b * NCHUNK + c]);
    float L = 0.f;
    #pragma unroll
    for (int c = 0; c < NCHUNK; c++)
        L += __expf(g_part_m[b * NCHUNK + c] - M) * g_part_l[b * NCHUNK + c];
    const float invL = 1.f / L;

    if (part == 8) {
        float4 ctx = make_float4(0.f, 0.f, 0.f, 0.f);
        #pragma unroll 4
        for (int c = 0; c < NCHUNK; c++) {
            const float ew = __expf(g_part_m[b * NCHUNK + c] - M);
            float4 v = ((const float4*)(g_part_acc + (size_t)(b * NCHUNK + c) * HH))[tid];
            ctx.x += ew * v.x; ctx.y += ew * v.y;
            ctx.z += ew * v.z; ctx.w += ew * v.w;
        }
        ctx.x *= invL; ctx.y *= invL; ctx.z *= invL; ctx.w *= invL;
        ((float4*)(out + (size_t)b * HH))[tid] = ctx;
    } else {
        float* wout = out + (size_t)BB * HH + (size_t)b * SS + part * 512;
        #pragma unroll
        for (int s = tid; s < 512; s += 256)
            wout[s] = __expf(wout[s] - M) * invL;
    }
}

extern "C" void kernel_launch(void* const* d_in, const int* in_sizes, int n_in,
                              void* d_out, int out_size)
{
    const float* query = nullptr;
    const float* keys  = nullptr;
    const int*   mask  = nullptr;
    const float* W     = nullptr;
    for (int i = 0; i < n_in; i++) {
        switch (in_sizes[i]) {
            case BB * HH:        query = (const float*)d_in[i]; break;  // 32768
            case BB * SS * HH:   keys  = (const float*)d_in[i]; break;  // 134217728
            case BB * SS:        mask  = (const int*)d_in[i];   break;  // 131072
            case HH * HH:        W     = (const float*)d_in[i]; break;  // 1048576
            default: break;
        }
    }
    float* out = (float*)d_out;

    proj_kernel<<<dim3(HH / 4, 4, 2), 128>>>(query, W);
    flash_kernel<<<dim3(NCHUNK, BB), 256>>>(keys, mask, out + (size_t)BB * HH);
    finalize_kernel<<<dim3(BB, 9), 256>>>(out);
}

// round 8
// speedup vs baseline: 1.1581x; 1.1581x over previous
#include <cuda_runtime.h>
#include <math.h>

#define BB 32
#define SS 4096
#define HH 1024
#define NCHUNK 64
#define CHUNK (SS / NCHUNK)            // 64 rows per CTA
#define TT 8                           // tile rows staged in smem
#define NT (CHUNK / TT)                // 8 tiles per CTA
#define NEG_BIG -1.0e9f

// ---- scratch (no allocations allowed) ----
__device__ float g_qp[2 * BB * HH];               // split-K projected-query partials
__device__ float g_part_m[BB * NCHUNK];           // per-chunk running max
__device__ float g_part_l[BB * NCHUNK];           // per-chunk exp-sum
__device__ float g_part_acc[BB * NCHUNK * HH];    // per-chunk unnormalized context (8MB)

// ============================================================
// Kernel A: split-K projection. [UNCHANGED — 14.0us measured]
// grid (HH/4, 4, 2) = 2048 CTAs, 128 threads (4 warps).
// ============================================================
__global__ void __launch_bounds__(128) proj_kernel(
    const float* __restrict__ query, const float* __restrict__ W)
{
    const int tid = threadIdx.x;
    const int w = tid >> 5, lane = tid & 31;
    const int o = blockIdx.x * 4 + w;
    const int b0 = blockIdx.y * 8;
    const int z = blockIdx.z;                      // k-half
    const int h0 = z * (HH / 2);                   // 0 or 512

    const float4* wrow = (const float4*)(W + (size_t)o * HH + h0);
    float4 wv[4];
    #pragma unroll
    for (int j = 0; j < 4; j++) wv[j] = wrow[j * 32 + lane];

    float p[8];
    #pragma unroll
    for (int bb = 0; bb < 8; bb++) {
        const float4* qq = (const float4*)(query + (size_t)(b0 + bb) * HH + h0);
        float s = 0.f;
        #pragma unroll
        for (int j = 0; j < 4; j++) {
            float4 qv = __ldg(qq + j * 32 + lane);
            s += wv[j].x * qv.x + wv[j].y * qv.y + wv[j].z * qv.z + wv[j].w * qv.w;
        }
        p[bb] = s;
    }

    #pragma unroll
    for (int off = 16; off > 0; off >>= 1) {
        #pragma unroll
        for (int bb = 0; bb < 8; bb++)
            p[bb] += __shfl_xor_sync(0xffffffffu, p[bb], off);
    }
    if (lane == 0) {
        float* dst = g_qp + (size_t)z * BB * HH;
        #pragma unroll
        for (int bb = 0; bb < 8; bb++)
            dst[(size_t)(b0 + bb) * HH + o] = p[bb];
    }
}

// ============================================================
// Kernel B: smem-staged fused flash.
// grid (NCHUNK, B) = 2048 CTAs, 256 threads (8 warps).
// Pipeline: GMEM -> prefetch regs (tile t+1) -> smem (tile t).
// Score phase (warp-per-row) and acc phase (thread-per-float4)
// both read smem; global loads decoupled from all compute.
// expf: 9 per tile total (warp 0), shared via smem.
// acc block-distributed -> no end-of-kernel warp combine.
// ============================================================
__global__ void __launch_bounds__(256) flash_kernel(
    const float* __restrict__ keys,
    const int* __restrict__ mask,
    float* __restrict__ scores_out)
{
    const int chunk = blockIdx.x, b = blockIdx.y;
    const int tid = threadIdx.x, w = tid >> 5, lane = tid & 31;

    __shared__ float4 sq[HH / 4];          // 4KB projected query
    __shared__ float4 buf[TT * (HH / 4)];  // 32KB key tile
    __shared__ float  s_scores[TT];
    __shared__ float  s_e[TT];
    __shared__ float  s_cfac;

    // q = sum of split-K partials
    {
        const float4* q0 = (const float4*)(g_qp);
        const float4* q1 = (const float4*)(g_qp + (size_t)BB * HH);
        const size_t base = (size_t)b * (HH / 4);
        for (int i = tid; i < HH / 4; i += 256) {
            float4 a = q0[base + i], c2 = q1[base + i];
            sq[i] = make_float4(a.x + c2.x, a.y + c2.y, a.z + c2.z, a.w + c2.w);
        }
    }

    const int s0 = chunk * CHUNK;
    const int* mrow = mask + (size_t)b * SS;
    const float4* kbase = (const float4*)(keys + ((size_t)b * SS + s0) * HH);
    const int TILE4 = TT * (HH / 4);       // 2048 float4 per tile

    // prologue: tile 0 -> regs -> smem
    float4 pf[8];
    #pragma unroll
    for (int j = 0; j < 8; j++) pf[j] = __ldcs(kbase + tid + j * 256);
    #pragma unroll
    for (int j = 0; j < 8; j++) buf[tid + j * 256] = pf[j];
    __syncthreads();

    float m = -INFINITY, l = 0.f;
    float4 acc = make_float4(0.f, 0.f, 0.f, 0.f);

    for (int t = 0; t < NT; t++) {
        // prefetch tile t+1 into regs (in flight during all compute below)
        if (t + 1 < NT) {
            const float4* kp = kbase + (size_t)(t + 1) * TILE4;
            #pragma unroll
            for (int j = 0; j < 8; j++) pf[j] = __ldcs(kp + tid + j * 256);
        }

        // ---- score phase: warp w computes row w of the tile ----
        {
            const float4* krow = buf + w * (HH / 4);
            float pa = 0.f, pb = 0.f;
            #pragma unroll
            for (int j = 0; j < 8; j += 2) {
                float4 k0 = krow[j * 32 + lane],       q0v = sq[j * 32 + lane];
                float4 k1 = krow[(j + 1) * 32 + lane], q1v = sq[(j + 1) * 32 + lane];
                pa += k0.x * q0v.x + k0.y * q0v.y + k0.z * q0v.z + k0.w * q0v.w;
                pb += k1.x * q1v.x + k1.y * q1v.y + k1.z * q1v.z + k1.w * q1v.w;
            }
            float p = pa + pb;
            #pragma unroll
            for (int off = 16; off > 0; off >>= 1)
                p += __shfl_xor_sync(0xffffffffu, p, off);
            const int s = s0 + t * TT + w;
            const float score = (mrow[s] != 0) ? NEG_BIG : p;
            if (lane == 0) {
                s_scores[w] = score;
                scores_out[(size_t)b * SS + s] = score;
            }
        }
        __syncthreads();   // A: scores visible

        // per-thread tile max & new running max (no expf)
        float tmax = s_scores[0];
        #pragma unroll
        for (int r = 1; r < TT; r++) tmax = fmaxf(tmax, s_scores[r]);
        const float mn = fmaxf(m, tmax);

        // warp 0 computes the 9 exp factors for the whole block
        if (w == 0) {
            if (lane < TT) s_e[lane] = __expf(s_scores[lane] - mn);
            if (lane == 0) s_cfac = __expf(m - mn);  // exp(-inf)=0 on tile 0
        }
        __syncthreads();   // B: e, cfac visible

        // ---- acc phase: thread owns float4 at h-position tid ----
        {
            const float c = s_cfac;
            float e[TT];
            #pragma unroll
            for (int r = 0; r < TT; r++) e[r] = s_e[r];
            float4 sum = make_float4(0.f, 0.f, 0.f, 0.f);
            #pragma unroll
            for (int r = 0; r < TT; r++) {
                float4 kv = buf[r * (HH / 4) + tid];
                sum.x += e[r] * kv.x; sum.y += e[r] * kv.y;
                sum.z += e[r] * kv.z; sum.w += e[r] * kv.w;
            }
            acc.x = acc.x * c + sum.x; acc.y = acc.y * c + sum.y;
            acc.z = acc.z * c + sum.z; acc.w = acc.w * c + sum.w;
            float esum = 0.f;
            #pragma unroll
            for (int r = 0; r < TT; r++) esum += e[r];
            l = l * c + esum;
            m = mn;
        }
        __syncthreads();   // C: all buf reads done

        // stage tile t+1 regs -> smem
        if (t + 1 < NT) {
            #pragma unroll
            for (int j = 0; j < 8; j++) buf[tid + j * 256] = pf[j];
            __syncthreads();   // D: new tile visible
        }
    }

    const int pidx = b * NCHUNK + chunk;
    ((float4*)(g_part_acc + (size_t)pidx * HH))[tid] = acc;
    if (tid == 0) { g_part_m[pidx] = m; g_part_l[pidx] = l; }
}

// ============================================================
// Kernel C: combine chunk partials -> context; normalize raw
// scores -> weights. grid (B, 9). [UNCHANGED]
// ============================================================
__global__ void __launch_bounds__(256) finalize_kernel(float* __restrict__ out)
{
    const int b = blockIdx.x, part = blockIdx.y, tid = threadIdx.x;

    float M = g_part_m[b * NCHUNK];
    #pragma unroll
    for (int c = 1; c < NCHUNK; c++) M = fmaxf(M, g_part_m[b * NCHUNK + c]);
    float L = 0.f;
    #pragma unroll
    for (int c = 0; c < NCHUNK; c++)
        L += __expf(g_part_m[b * NCHUNK + c] - M) * g_part_l[b * NCHUNK + c];
    const float invL = 1.f / L;

    if (part == 8) {
        float4 ctx = make_float4(0.f, 0.f, 0.f, 0.f);
        #pragma unroll 4
        for (int c = 0; c < NCHUNK; c++) {
            const float ew = __expf(g_part_m[b * NCHUNK + c] - M);
            float4 v = ((const float4*)(g_part_acc + (size_t)(b * NCHUNK + c) * HH))[tid];
            ctx.x += ew * v.x; ctx.y += ew * v.y;
            ctx.z += ew * v.z; ctx.w += ew * v.w;
        }
        ctx.x *= invL; ctx.y *= invL; ctx.z *= invL; ctx.w *= invL;
        ((float4*)(out + (size_t)b * HH))[tid] = ctx;
    } else {
        float* wout = out + (size_t)BB * HH + (size_t)b * SS + part * 512;
        #pragma unroll
        for (int s = tid; s < 512; s += 256)
            wout[s] = __expf(wout[s] - M) * invL;
    }
}

extern "C" void kernel_launch(void* const* d_in, const int* in_sizes, int n_in,
                              void* d_out, int out_size)
{
    const float* query = nullptr;
    const float* keys  = nullptr;
    const int*   mask  = nullptr;
    const float* W     = nullptr;
    for (int i = 0; i < n_in; i++) {
        switch (in_sizes[i]) {
            case BB * HH:        query = (const float*)d_in[i]; break;  // 32768
            case BB * SS * HH:   keys  = (const float*)d_in[i]; break;  // 134217728
            case BB * SS:        mask  = (const int*)d_in[i];   break;  // 131072
            case HH * HH:        W     = (const float*)d_in[i]; break;  // 1048576
            default: break;
        }
    }
    float* out = (float*)d_out;

    proj_kernel<<<dim3(HH / 4, 4, 2), 128>>>(query, W);
    flash_kernel<<<dim3(NCHUNK, BB), 256>>>(keys, mask, out + (size_t)BB * HH);
    finalize_kernel<<<dim3(BB, 9), 256>>>(out);
}

// round 9
// speedup vs baseline: 1.8741x; 1.6182x over previous
#include <cuda_runtime.h>
#include <math.h>

#define BB 32
#define SS 4096
#define HH 1024
#define NCHUNK 32
#define CHUNK (SS / NCHUNK)            // 128 rows per CTA
#define ROWS_PER_WARP (CHUNK / 8)      // 16 rows per warp
#define NEG_BIG -1.0e9f

// ---- scratch (no allocations allowed) ----
__device__ float g_qp[2 * BB * HH];               // split-K projected-query partials
__device__ float g_part_m[BB * NCHUNK];           // per-chunk running max
__device__ float g_part_l[BB * NCHUNK];           // per-chunk exp-sum
__device__ float g_part_acc[BB * NCHUNK * HH];    // per-chunk unnormalized context (4MB)

// ============================================================
// Kernel A: split-K projection. [UNCHANGED — 14.0us measured]
// grid (HH/4, 4, 2) = 2048 CTAs, 128 threads (4 warps).
// ============================================================
__global__ void __launch_bounds__(128) proj_kernel(
    const float* __restrict__ query, const float* __restrict__ W)
{
    const int tid = threadIdx.x;
    const int w = tid >> 5, lane = tid & 31;
    const int o = blockIdx.x * 4 + w;
    const int b0 = blockIdx.y * 8;
    const int z = blockIdx.z;                      // k-half
    const int h0 = z * (HH / 2);                   // 0 or 512

    const float4* wrow = (const float4*)(W + (size_t)o * HH + h0);
    float4 wv[4];
    #pragma unroll
    for (int j = 0; j < 4; j++) wv[j] = wrow[j * 32 + lane];

    float p[8];
    #pragma unroll
    for (int bb = 0; bb < 8; bb++) {
        const float4* qq = (const float4*)(query + (size_t)(b0 + bb) * HH + h0);
        float s = 0.f;
        #pragma unroll
        for (int j = 0; j < 4; j++) {
            float4 qv = __ldg(qq + j * 32 + lane);
            s += wv[j].x * qv.x + wv[j].y * qv.y + wv[j].z * qv.z + wv[j].w * qv.w;
        }
        p[bb] = s;
    }

    #pragma unroll
    for (int off = 16; off > 0; off >>= 1) {
        #pragma unroll
        for (int bb = 0; bb < 8; bb++)
            p[bb] += __shfl_xor_sync(0xffffffffu, p[bb], off);
    }
    if (lane == 0) {
        float* dst = g_qp + (size_t)z * BB * HH;
        #pragma unroll
        for (int bb = 0; bb < 8; bb++)
            dst[(size_t)(b0 + bb) * HH + o] = p[bb];
    }
}

// ============================================================
// Kernel B: fused scores + online softmax + context partial,
// WITH MASK SKIP. grid (NCHUNK, B) = 1024 CTAs, 256 threads
// (8 warps), warp-per-row (R5 architecture).
// ~50% of rows are masked: their weight is exactly 0 in fp32
// (exp(-1e9 - M) underflows), so the key row is never read —
// halves the keys stream. Warp-uniform branch, no divergence.
// Exactness of skip: within a chunk a masked-prefix is flushed
// by c=exp(-1e9-score)=0; an all-masked chunk has m=-1e9 and
// finalize scales its acc by exp(-1e9-M_global)=0.
// ============================================================
__global__ void __launch_bounds__(256) flash_kernel(
    const float* __restrict__ keys,
    const int* __restrict__ mask,
    float* __restrict__ scores_out)
{
    const int chunk = blockIdx.x, b = blockIdx.y;
    const int tid = threadIdx.x, w = tid >> 5, lane = tid & 31;

    __shared__ float4 sq[HH / 4];          // 4KB projected query (sum of partials)
    __shared__ float  s_m[8], s_l[8];
    __shared__ float4 s_acc[8][256];       // 32KB warp partial contexts

    {
        const float4* q0 = (const float4*)(g_qp);
        const float4* q1 = (const float4*)(g_qp + (size_t)BB * HH);
        const size_t base = (size_t)b * (HH / 4);
        for (int i = tid; i < HH / 4; i += 256) {
            float4 a = q0[base + i], c2 = q1[base + i];
            sq[i] = make_float4(a.x + c2.x, a.y + c2.y, a.z + c2.z, a.w + c2.w);
        }
    }
    __syncthreads();

    float4 acc[8];
    #pragma unroll
    for (int j = 0; j < 8; j++) acc[j] = make_float4(0.f, 0.f, 0.f, 0.f);
    float m = -INFINITY, l = 0.f;

    const int s0 = chunk * CHUNK + w * ROWS_PER_WARP;
    const int* mrow = mask + (size_t)b * SS;

    #pragma unroll 2
    for (int r = 0; r < ROWS_PER_WARP; r++) {
        const int s = s0 + r;

        if (mrow[s] != 0) {
            // ---- masked row: weight is exactly 0; skip the key read ----
            if (lane == 0) scores_out[(size_t)b * SS + s] = NEG_BIG;
            const float mn = fmaxf(m, NEG_BIG);
            const float c  = __expf(m - mn);        // 0 if m was -inf
            const float e  = __expf(NEG_BIG - mn);  // 1 iff mn==NEG_BIG, else 0
            l = l * c + e;
            m = mn;
            // acc untouched: either e==0, or acc is still all-zero and the
            // omitted e*kv term is annihilated downstream by an exact 0 scale.
            continue;
        }

        const float4* kp = (const float4*)(keys + ((size_t)b * SS + s) * HH);
        float4 kv[8];
        float p = 0.f;
        #pragma unroll
        for (int j = 0; j < 8; j++) {
            kv[j] = __ldcs(kp + j * 32 + lane);
            float4 qv = sq[j * 32 + lane];
            p += kv[j].x * qv.x + kv[j].y * qv.y +
                 kv[j].z * qv.z + kv[j].w * qv.w;
        }
        #pragma unroll
        for (int off = 16; off > 0; off >>= 1)
            p += __shfl_xor_sync(0xffffffffu, p, off);

        if (lane == 0) scores_out[(size_t)b * SS + s] = p;

        // online softmax update; key row still in registers
        const float mn = fmaxf(m, p);
        const float c  = __expf(m - mn);      // exp(-inf)=0 on first unmasked
        const float e  = __expf(p - mn);
        l = l * c + e;
        #pragma unroll
        for (int j = 0; j < 8; j++) {
            acc[j].x = acc[j].x * c + e * kv[j].x;
            acc[j].y = acc[j].y * c + e * kv[j].y;
            acc[j].z = acc[j].z * c + e * kv[j].z;
            acc[j].w = acc[j].w * c + e * kv[j].w;
        }
        m = mn;
    }

    // ---- combine 8 warps within the block ----
    if (lane == 0) { s_m[w] = m; s_l[w] = l; }
    #pragma unroll
    for (int j = 0; j < 8; j++) s_acc[w][j * 32 + lane] = acc[j];
    __syncthreads();

    float M = s_m[0];
    #pragma unroll
    for (int i = 1; i < 8; i++) M = fmaxf(M, s_m[i]);
    float ew[8], L = 0.f;
    #pragma unroll
    for (int i = 0; i < 8; i++) { ew[i] = __expf(s_m[i] - M); L += ew[i] * s_l[i]; }

    float4 cacc = make_float4(0.f, 0.f, 0.f, 0.f);
    #pragma unroll
    for (int i = 0; i < 8; i++) {
        float4 v = s_acc[i][tid];
        cacc.x += ew[i] * v.x; cacc.y += ew[i] * v.y;
        cacc.z += ew[i] * v.z; cacc.w += ew[i] * v.w;
    }
    const int pidx = b * NCHUNK + chunk;
    ((float4*)(g_part_acc + (size_t)pidx * HH))[tid] = cacc;
    if (tid == 0) { g_part_m[pidx] = M; g_part_l[pidx] = L; }
}

// ============================================================
// Kernel C: combine chunk partials -> context; normalize raw
// scores -> weights. grid (B, 9). [structure unchanged]
// ============================================================
__global__ void __launch_bounds__(256) finalize_kernel(float* __restrict__ out)
{
    const int b = blockIdx.x, part = blockIdx.y, tid = threadIdx.x;

    float M = g_part_m[b * NCHUNK];
    #pragma unroll
    for (int c = 1; c < NCHUNK; c++) M = fmaxf(M, g_part_m[b * NCHUNK + c]);
    float L = 0.f;
    #pragma unroll
    for (int c = 0; c < NCHUNK; c++)
        L += __expf(g_part_m[b * NCHUNK + c] - M) * g_part_l[b * NCHUNK + c];
    const float invL = 1.f / L;

    if (part == 8) {
        float4 ctx = make_float4(0.f, 0.f, 0.f, 0.f);
        #pragma unroll 4
        for (int c = 0; c < NCHUNK; c++) {
            const float ew = __expf(g_part_m[b * NCHUNK + c] - M);
            float4 v = ((const float4*)(g_part_acc + (size_t)(b * NCHUNK + c) * HH))[tid];
            ctx.x += ew * v.x; ctx.y += ew * v.y;
            ctx.z += ew * v.z; ctx.w += ew * v.w;
        }
        ctx.x *= invL; ctx.y *= invL; ctx.z *= invL; ctx.w *= invL;
        ((float4*)(out + (size_t)b * HH))[tid] = ctx;
    } else {
        float* wout = out + (size_t)BB * HH + (size_t)b * SS + part * 512;
        #pragma unroll
        for (int s = tid; s < 512; s += 256)
            wout[s] = __expf(wout[s] - M) * invL;
    }
}

extern "C" void kernel_launch(void* const* d_in, const int* in_sizes, int n_in,
                              void* d_out, int out_size)
{
    const float* query = nullptr;
    const float* keys  = nullptr;
    const int*   mask  = nullptr;
    const float* W     = nullptr;
    for (int i = 0; i < n_in; i++) {
        switch (in_sizes[i]) {
            case BB * HH:        query = (const float*)d_in[i]; break;  // 32768
            case BB * SS * HH:   keys  = (const float*)d_in[i]; break;  // 134217728
            case BB * SS:        mask  = (const int*)d_in[i];   break;  // 131072
            case HH * HH:        W     = (const float*)d_in[i]; break;  // 1048576
            default: break;
        }
    }
    float* out = (float*)d_out;

    proj_kernel<<<dim3(HH / 4, 4, 2), 128>>>(query, W);
    flash_kernel<<<dim3(NCHUNK, BB), 256>>>(keys, mask, out + (size_t)BB * HH);
    finalize_kernel<<<dim3(BB, 9), 256>>>(out);
}